// round 7
// baseline (speedup 1.0000x reference)
#include <cuda_runtime.h>
#include <cuda_bf16.h>

#define NN 8192
#define NPAIRS (NN / 2)
#define SLOTS 1024u           // per-pair edge capacity (λ≈19 → never overflows)
#define OVF_CAP (1u << 20)    // safety spill buffer

// Static scratch (no allocation allowed anywhere). No persistent parent
// array — connectivity is solved in shared memory each run.
__device__ unsigned int d_ucount;            // strictly-upper positives
__device__ unsigned int d_dcount;            // diagonal positives
__device__ unsigned int d_ecnt[NPAIRS];      // edges per pair-block (overwritten each run)
__device__ unsigned int d_edges[NPAIRS * SLOTS];
__device__ unsigned int d_ovfcnt;            // overflow spill count
__device__ unsigned int d_ovf[OVF_CAP];

// Upper-triangle scan, block per row pair (row, NN-1-row): NN+1 elements per
// block. Hot loop: 4 batched LDG.128, straight-line counting, one uniform
// warp branch via ballot. Edges append to a per-block slice (smem counter +
// STG) — no calls or divergent latency chains in the stream (measured
// ~4.3 TB/s in R6).
// Exactness: adj is bitwise symmetric -> full positives = 2U + D, and the
// reference's sum//2 = U + D//2 exactly.
__global__ void __launch_bounds__(256) hc_scan(const float* __restrict__ adj) {
    __shared__ unsigned int s_cnt;
    const int t = threadIdx.x;
    const int pair = blockIdx.x;
    const unsigned ebase = (unsigned)pair * SLOTS;
    if (t == 0) s_cnt = 0u;
    __syncthreads();

    unsigned int cnt = 0;

    #pragma unroll
    for (int half = 0; half < 2; half++) {
        const int row = half ? (NN - 1 - pair) : pair;
        const float4* __restrict__ rowp = (const float4*)(adj + (size_t)row * NN);
        const int start4 = row >> 2;           // quad containing the diagonal
        const unsigned enc_row = (unsigned)row << 13;

        if (t == 0) {
            // diagonal quad: cols may be <, ==, or > row
            float4 v = rowp[start4];
            int col0 = start4 << 2;
            float e[4] = {v.x, v.y, v.z, v.w};
            unsigned dd = 0;
            #pragma unroll
            for (int j = 0; j < 4; j++) {
                int col = col0 + j;
                if (e[j] > 0.0f) {
                    if (col == row) dd++;
                    else if (col > row) {
                        cnt++;
                        unsigned base = atomicAdd(&s_cnt, 1u);
                        if (base < SLOTS) d_edges[ebase + base] = enc_row | (unsigned)col;
                        else {
                            unsigned o = atomicAdd(&d_ovfcnt, 1u);
                            if (o < OVF_CAP) d_ovf[o] = enc_row | (unsigned)col;
                        }
                    }
                }
            }
            if (dd) atomicAdd(&d_dcount, dd);
        }

        const int lim = NN / 4;
        for (int ib = start4 + 1; ib < lim; ib += 1024) {
            const float4 NEG = make_float4(-1.f, -1.f, -1.f, -1.f);
            const int i0 = ib + t;
            float4 v0 = NEG, v1 = NEG, v2 = NEG, v3 = NEG;
            if (i0       < lim) v0 = rowp[i0];
            if (i0 + 256 < lim) v1 = rowp[i0 + 256];
            if (i0 + 512 < lim) v2 = rowp[i0 + 512];
            if (i0 + 768 < lim) v3 = rowp[i0 + 768];

            unsigned k0 = (unsigned)(v0.x > 0.f) + (unsigned)(v0.y > 0.f)
                        + (unsigned)(v0.z > 0.f) + (unsigned)(v0.w > 0.f);
            unsigned k1 = (unsigned)(v1.x > 0.f) + (unsigned)(v1.y > 0.f)
                        + (unsigned)(v1.z > 0.f) + (unsigned)(v1.w > 0.f);
            unsigned k2 = (unsigned)(v2.x > 0.f) + (unsigned)(v2.y > 0.f)
                        + (unsigned)(v2.z > 0.f) + (unsigned)(v2.w > 0.f);
            unsigned k3 = (unsigned)(v3.x > 0.f) + (unsigned)(v3.y > 0.f)
                        + (unsigned)(v3.z > 0.f) + (unsigned)(v3.w > 0.f);
            unsigned k = k0 + k1 + k2 + k3;
            cnt += k;

            if (__ballot_sync(0xFFFFFFFFu, k != 0u)) {
                if (k) {
                    unsigned idx = atomicAdd(&s_cnt, k);
                    #pragma unroll
                    for (int q = 0; q < 4; q++) {
                        float4 v = (q == 0) ? v0 : (q == 1) ? v1 : (q == 2) ? v2 : v3;
                        int col0 = (i0 + q * 256) << 2;
                        float e[4] = {v.x, v.y, v.z, v.w};
                        #pragma unroll
                        for (int j = 0; j < 4; j++) {
                            if (e[j] > 0.f) {
                                if (idx < SLOTS)
                                    d_edges[ebase + idx] = enc_row | (unsigned)(col0 + j);
                                else {
                                    unsigned o = atomicAdd(&d_ovfcnt, 1u);
                                    if (o < OVF_CAP) d_ovf[o] = enc_row | (unsigned)(col0 + j);
                                }
                                idx++;
                            }
                        }
                    }
                }
            }
        }
    }

    for (int s = 16; s > 0; s >>= 1)
        cnt += __shfl_down_sync(0xFFFFFFFFu, cnt, s);
    __shared__ unsigned int shu[8];
    int lane = t & 31, w = t >> 5;
    if (lane == 0) shu[w] = cnt;
    __syncthreads();
    if (t == 0) {
        unsigned su = 0;
        #pragma unroll
        for (int i = 0; i < 8; i++) su += shu[i];
        atomicAdd(&d_ucount, su);
        d_ecnt[pair] = min(s_cnt, SLOTS);
    }
}

// Shared-memory union-find (LDS 29cyc / ATOMS ~32cyc vs 234-318cyc in L2):
// path halving + CAS hooking toward the smaller root. Benign races: smem is
// block-coherent; halving writes always point at an ancestor.
__device__ __forceinline__ void uf_union_s(int* sp, int a, int b) {
    while (true) {
        while (true) {                       // find(a)
            int p = sp[a];
            if (p == a) break;
            int gp = sp[p];
            if (gp == p) { a = p; break; }
            sp[a] = gp; a = gp;
        }
        while (true) {                       // find(b)
            int p = sp[b];
            if (p == b) break;
            int gp = sp[p];
            if (gp == p) { b = p; break; }
            sp[b] = gp; b = gp;
        }
        if (a == b) return;
        int lo = min(a, b);
        int hi = max(a, b);
        int old = atomicCAS(&sp[hi], hi, lo);
        if (old == hi) return;
        a = lo;
        b = old;
    }
}

// Single block: union all buffered edges in smem, count roots, compute the
// loss, reset counters for the next replay. No persistent parent state.
__global__ void __launch_bounds__(1024) hc_finish(float* __restrict__ out) {
    __shared__ int sp[NN];                   // 32KB parent array
    __shared__ int sh[1024];
    const int t = threadIdx.x;

    #pragma unroll
    for (int k = 0; k < NN / 1024; k++)
        sp[t + k * 1024] = t + k * 1024;
    __syncthreads();

    // main edge buffer: thread-strided over pairs (~4 pairs * ~19 edges each)
    for (int p = t; p < NPAIRS; p += 1024) {
        unsigned n = d_ecnt[p];
        const unsigned base = (unsigned)p * SLOTS;
        for (unsigned i = 0; i < n; i++) {
            unsigned e = d_edges[base + i];
            uf_union_s(sp, (int)(e >> 13), (int)(e & 8191u));
        }
    }
    // overflow spill (normally empty)
    unsigned novf = min(d_ovfcnt, OVF_CAP);
    for (unsigned i = t; i < novf; i += 1024) {
        unsigned e = d_ovf[i];
        uf_union_s(sp, (int)(e >> 13), (int)(e & 8191u));
    }
    __syncthreads();

    int roots = 0;
    #pragma unroll
    for (int k = 0; k < NN / 1024; k++) {
        int i = t + k * 1024;
        roots += (sp[i] == i) ? 1 : 0;
    }
    sh[t] = roots;
    __syncthreads();
    for (int s = 512; s > 0; s >>= 1) {
        if (t < s) sh[t] += sh[t + s];
        __syncthreads();
    }
    if (t == 0) {
        float n_comp  = (float)sh[0];
        unsigned half_edges = d_ucount + (d_dcount >> 1);   // (2U+D)//2
        float n_edges = (float)half_edges;
        float betti1  = n_edges - (float)NN + n_comp;
        float n_cyc   = fmaxf(0.0f, betti1);
        float comp_l  = (n_comp - 1.0f) * (n_comp - 1.0f);
        out[0] = comp_l + n_cyc * n_cyc;
        // reset accumulators for the next replay
        d_ucount = 0u; d_dcount = 0u; d_ovfcnt = 0u;
    }
}

extern "C" void kernel_launch(void* const* d_in, const int* in_sizes, int n_in,
                              void* d_out, int out_size) {
    const float* adj = (const float*)d_in[0];
    float* out = (float*)d_out;

    hc_scan<<<NPAIRS, 256>>>(adj);
    hc_finish<<<1, 1024>>>(out);
}